// round 6
// baseline (speedup 1.0000x reference)
#include <cuda_runtime.h>

// CRF negative log-likelihood, specialized to L=64 live states.
//
// Key identities (exact w.r.t. the reference's fp32 underflow behavior):
//   alpha_1[j]  = pred[b,0,j] + trans[64][j]
//   alpha_t[j]  = pred[b,t-1,j] + M + log( sum_i exp(alpha_{t-1}[i]-M) * E[i][j] ),
//                 E[i][j] = exp(trans[i][j]),  t = 2..seq_len
//   logZ_b      = logsumexp_i( alpha_{seq}[i] + trans[i][65] )
//   gold_b      = sum_{t<seq} pred[b,t,ref[t]]
//               + trans[64][ref[0]] + sum_{1<=t<seq} trans[ref[t-1]][ref[t]]
//               + trans[ref[seq-1]][65]
//   loss        = sum_b (logZ_b - gold_b)

__device__ float g_partial[4096];

__device__ __forceinline__ float warp_rmax(float v) {
#pragma unroll
    for (int o = 16; o > 0; o >>= 1)
        v = fmaxf(v, __shfl_xor_sync(0xffffffffu, v, o));
    return v;
}
__device__ __forceinline__ float warp_rsum(float v) {
#pragma unroll
    for (int o = 16; o > 0; o >>= 1)
        v += __shfl_xor_sync(0xffffffffu, v, o);
    return v;
}

struct __align__(16) HalfSh {
    float4 e[2][16];   // double-buffered exp(alpha - M), 64 floats each
    float  wm[2][2];   // double-buffered per-warp max exchange
    float  fin[4];     // final reduction scratch
};

__global__ void __launch_bounds__(128, 1)
crf_forward_kernel(const float* __restrict__ pred,
                   const float* __restrict__ trans,
                   const int*   __restrict__ ref,
                   const int*   __restrict__ slen,
                   int B, int T)
{
    __shared__ HalfSh hs[2];
    const int tid  = threadIdx.x;
    const int half = tid >> 6;          // 2 independent batches per CTA
    const int j    = tid & 63;          // state column owned by this thread
    const int wih  = (tid >> 5) & 1;    // warp index within the half
    const int lane = tid & 31;
    const int b    = blockIdx.x * 2 + half;
    if (b >= B) return;

    HalfSh& S = hs[half];
    const int barid = 1 + half;         // named barrier per half (ids 1,2)

    const float* pb = pred + (size_t)b * T * 64;
    const int*   rb = ref  + (size_t)b * T;
    const int    seq = slen[b];

    // E column j into registers: E[i] = exp(trans[i][j])
    float E[64];
#pragma unroll
    for (int i = 0; i < 64; ++i)
        E[i] = __expf(trans[i * 66 + j]);

    // ---- gold path score, parallel over time ----
    float gold = 0.0f;
    for (int t = j; t < seq; t += 64) {
        int r  = rb[t];
        int rp = (t == 0) ? 64 : rb[t - 1];
        gold += pb[(size_t)t * 64 + r];
        gold += trans[rp * 66 + r];
        if (t == seq - 1) gold += trans[r * 66 + 65];
    }

    // ---- forward recursion ----
    float alpha = pb[j] + trans[64 * 66 + j];    // alpha_1

    // bootstrap the delayed-max pipeline (uses parity-1 wm slots)
    float wred = warp_rmax(alpha);
    if (lane == 0) S.wm[1][wih] = wred;
    asm volatile("bar.sync %0, 64;" :: "r"(barid) : "memory");
    float M = fmaxf(S.wm[1][0], S.wm[1][1]) + 24.0f;

    // pred prefetch pipeline, depth 2 (row t-1 consumed at step t)
    float pv0 = pb[(size_t)min(1, seq - 1) * 64 + j];
    float pv1 = pb[(size_t)min(2, seq - 1) * 64 + j];

    int par = 0;
    for (int t = 2; t <= seq; ++t) {
        // scale current alpha and publish
        float ev = __expf(alpha - M);
        reinterpret_cast<float*>(S.e[par])[j] = ev;
        if (lane == 0) S.wm[par][wih] = wred;
        asm volatile("bar.sync %0, 64;" :: "r"(barid) : "memory");
        float Mn = fmaxf(S.wm[par][0], S.wm[par][1]) + 24.0f;

        // start reduction of alpha_{t-1}; its result is consumed at step t+1,
        // so the 5xSHFL latency hides under the matvec below.
        float rr = warp_rmax(alpha);

        // s_j = sum_i e[i] * E[i][j]   (broadcast LDS.128 + 64 FFMA)
        float a0 = 0.f, a1 = 0.f, a2 = 0.f, a3 = 0.f;
        const float4* evv = S.e[par];
#pragma unroll
        for (int k = 0; k < 16; ++k) {
            float4 v = evv[k];
            a0 = fmaf(v.x, E[4 * k + 0], a0);
            a1 = fmaf(v.y, E[4 * k + 1], a1);
            a2 = fmaf(v.z, E[4 * k + 2], a2);
            a3 = fmaf(v.w, E[4 * k + 3], a3);
        }
        float s = (a0 + a1) + (a2 + a3);
        alpha = (pv0 + M) + __logf(s);

        pv0 = pv1;
        pv1 = pb[(size_t)min(t + 1, seq - 1) * 64 + j];
        M    = Mn;
        wred = rr;
        par ^= 1;
    }

    // ---- logZ = logsumexp_j( alpha + trans[j][65] ) ----
    float v = alpha + trans[j * 66 + 65];
    float m = warp_rmax(v);
    if (lane == 0) S.fin[wih] = m;
    asm volatile("bar.sync %0, 64;" :: "r"(barid) : "memory");
    float M2 = fmaxf(S.fin[0], S.fin[1]);
    float es = warp_rsum(__expf(v - M2));
    float gs = warp_rsum(gold);
    if (lane == 0) { S.fin[2 + wih] = es; S.wm[0][wih] = gs; }
    asm volatile("bar.sync %0, 64;" :: "r"(barid) : "memory");
    if (j == 0) {
        float logZ  = M2 + __logf(S.fin[2] + S.fin[3]);
        float goldT = S.wm[0][0] + S.wm[0][1];
        g_partial[b] = logZ - goldT;
    }
}

// Deterministic final reduction (fixed-order tree), writes the scalar output.
__global__ void crf_reduce_kernel(float* out, int B, int out_size)
{
    __shared__ float sh[256];
    int t = threadIdx.x;
    float s = 0.0f;
    for (int i = t; i < B; i += 256) s += g_partial[i];
    sh[t] = s;
    __syncthreads();
    for (int w = 128; w > 0; w >>= 1) {
        if (t < w) sh[t] += sh[t + w];
        __syncthreads();
    }
    if (t == 0) out[0] = sh[0];
    for (int i = t + 1; i < out_size; i += 256) out[i] = 0.0f;  // only thread strides cover i>0
}

extern "C" void kernel_launch(void* const* d_in, const int* in_sizes, int n_in,
                              void* d_out, int out_size)
{
    // Identify inputs by element count (robust to metadata ordering):
    //   trans = 66*66 = 4356, pred = largest, seq_len = smallest, ref = the rest.
    int it = -1;
    for (int i = 0; i < n_in; ++i)
        if (in_sizes[i] == 66 * 66) { it = i; break; }
    int ip = -1, is = -1;
    for (int i = 0; i < n_in; ++i) {
        if (i == it) continue;
        if (ip < 0 || in_sizes[i] > in_sizes[ip]) ip = i;
        if (is < 0 || in_sizes[i] < in_sizes[is]) is = i;
    }
    int ir = -1;
    for (int i = 0; i < n_in; ++i)
        if (i != it && i != ip && i != is) { ir = i; break; }

    const float* pred  = (const float*)d_in[ip];
    const float* trans = (const float*)d_in[it];
    const int*   ref   = (const int*)d_in[ir];
    const int*   slen  = (const int*)d_in[is];

    const int B = in_sizes[is];
    const int T = in_sizes[ir] / B;

    crf_forward_kernel<<<(B + 1) / 2, 128>>>(pred, trans, ref, slen, B, T);
    crf_reduce_kernel<<<1, 256>>>((float*)d_out, B, out_size);
}

// round 7
// speedup vs baseline: 1.3982x; 1.3982x over previous
#include <cuda_runtime.h>

// CRF negative log-likelihood, L=64 live states, exp-domain recursion.
//
//   v_t[j]  = (sum_i v_{t-1}[i] * E[i][j]) * exp(pred[b,t-1,j]) * 2^{-ex_t}
//   E[i][j] = exp(trans[i][j]); ex_t = floor(log2(max v_{t-2})) >> 1 (damped,
//             exact power-of-two scale; ks = sum ex_t tracked as int)
//   logZ_b  = m0 + ks*ln2 + log( sum_j v_seq[j] * exp(trans[j][65]) )
//   gold_b  = sum_t pred[b,t,ref_t] + trans[64][ref_0]
//           + sum trans[ref_{t-1}][ref_t] + trans[ref_{seq-1}][65]

__device__ double g_partial[4096];

__device__ __forceinline__ float warp_rmax(float v) {
#pragma unroll
    for (int o = 16; o > 0; o >>= 1)
        v = fmaxf(v, __shfl_xor_sync(0xffffffffu, v, o));
    return v;
}
__device__ __forceinline__ float warp_rsum(float v) {
#pragma unroll
    for (int o = 16; o > 0; o >>= 1)
        v += __shfl_xor_sync(0xffffffffu, v, o);
    return v;
}

typedef unsigned long long u64;
__device__ __forceinline__ u64 ffma2(u64 a, u64 b, u64 c) {
    u64 d;
    asm("fma.rn.f32x2 %0, %1, %2, %3;" : "=l"(d) : "l"(a), "l"(b), "l"(c));
    return d;
}
__device__ __forceinline__ u64 fadd2(u64 a, u64 b) {
    u64 d;
    asm("add.rn.f32x2 %0, %1, %2;" : "=l"(d) : "l"(a), "l"(b));
    return d;
}
__device__ __forceinline__ u64 pack2(float lo, float hi) {
    u64 d;
    asm("mov.b64 %0, {%1, %2};" : "=l"(d) : "f"(lo), "f"(hi));
    return d;
}

struct __align__(16) HalfSh {
    float4 e[2][16];   // double-buffered v vector (64 floats)
    float  wm[2][2];   // double-buffered per-warp max exchange
    float  fin[4];     // final reduction scratch
};

__global__ void __launch_bounds__(128, 1)
crf_forward_kernel(const float* __restrict__ pred,
                   const float* __restrict__ trans,
                   const int*   __restrict__ ref,
                   const int*   __restrict__ slen,
                   int B, int T)
{
    __shared__ HalfSh hs[2];
    const int tid  = threadIdx.x;
    const int half = tid >> 6;          // 2 independent batches per CTA
    const int j    = tid & 63;          // state column owned by this thread
    const int wih  = (tid >> 5) & 1;    // warp index within the half
    const int lane = tid & 31;
    const int b    = blockIdx.x * 2 + half;
    if (b >= B) return;

    HalfSh& S = hs[half];
    const int barid = 1 + half;         // named barrier per half

    const float* pb  = pred + (size_t)b * T * 64;
    const int*   rb  = ref  + (size_t)b * T;
    const int    seq = slen[b];

    // E column j as 32 packed f32x2 pairs: E2[p] = (exp(T[2p][j]), exp(T[2p+1][j]))
    u64 E2[32];
#pragma unroll
    for (int p = 0; p < 32; ++p) {
        float e0 = __expf(trans[(2 * p) * 66 + j]);
        float e1 = __expf(trans[(2 * p + 1) * 66 + j]);
        E2[p] = pack2(e0, e1);
    }

    // ---- gold path score, parallel over time ----
    float gold = 0.0f;
    for (int t = j; t < seq; t += 64) {
        int r  = rb[t];
        int rp = (t == 0) ? 64 : rb[t - 1];
        gold += pb[(size_t)t * 64 + r];
        gold += trans[rp * 66 + r];
        if (t == seq - 1) gold += trans[r * 66 + 65];
    }

    // ---- bootstrap: v_1 = exp(alpha_1 - m0), exact max m0 ----
    float alpha1 = pb[j] + trans[64 * 66 + j];
    float wmax = warp_rmax(alpha1);
    if (lane == 0) S.wm[0][wih] = wmax;
    asm volatile("bar.sync %0, 64;" :: "r"(barid) : "memory");
    float m0 = fmaxf(S.wm[0][0], S.wm[0][1]);
    float v  = __expf(alpha1 - m0);

    int    ks   = 0;            // exact sum of power-of-two scalings
    float  wred = 1.0f;         // delayed-max pipeline bootstrap (max v_1 = 1)

    // prefetch pipeline: P_cur = exp(pred row t-1) for the current step
    float P_cur = __expf(pb[(size_t)min(1, seq - 1) * 64 + j]);
    float pv_a  = pb[(size_t)min(2, seq - 1) * 64 + j];
    float pv_b  = pb[(size_t)min(3, seq - 1) * 64 + j];

    int par = 0;
    for (int t = 2; t <= seq; ++t) {
        // publish v_{t-1} and the delayed warp max
        reinterpret_cast<float*>(S.e[par])[j] = v;
        if (lane == 0) S.wm[par][wih] = wred;
        asm volatile("bar.sync %0, 64;" :: "r"(barid) : "memory");
        float m2 = fmaxf(S.wm[par][0], S.wm[par][1]);

        // start max reduction of v_{t-1}; consumed next iteration (latency hidden)
        float rr = warp_rmax(v);

        // half-damped exact power-of-two rescale (stable: roots (1±i)/2)
        int   ex = ((__float_as_int(m2) >> 23) - 127) >> 1;
        float rs = __int_as_float((127 - ex) << 23);   // exact 2^-ex
        float factor = P_cur * rs;
        ks += ex;

        // s_j = sum_i v_i * E[i][j]  — 16x LDS.128 + 32x FFMA2
        const ulonglong2* evv = reinterpret_cast<const ulonglong2*>(S.e[par]);
        u64 a0 = 0ull, a1 = 0ull, a2 = 0ull, a3 = 0ull;
#pragma unroll
        for (int k = 0; k < 16; k += 2) {
            ulonglong2 q0 = evv[k];
            ulonglong2 q1 = evv[k + 1];
            a0 = ffma2(q0.x, E2[2 * k + 0], a0);
            a1 = ffma2(q0.y, E2[2 * k + 1], a1);
            a2 = ffma2(q1.x, E2[2 * k + 2], a2);
            a3 = ffma2(q1.y, E2[2 * k + 3], a3);
        }
        u64 s2 = fadd2(fadd2(a0, a2), fadd2(a1, a3));
        float slo, shi;
        asm("mov.b64 {%0, %1}, %2;" : "=f"(slo), "=f"(shi) : "l"(s2));
        v = (slo + shi) * factor;

        // rotate prefetch (exp off the critical chain)
        P_cur = __expf(pv_a);
        pv_a  = pv_b;
        pv_b  = pb[(size_t)min(t + 2, seq - 1) * 64 + j];
        wred  = rr;
        par  ^= 1;
    }

    // ---- logZ = m0 + ks*ln2 + log( sum_j v_j * exp(trans[j][65]) ) ----
    float w  = v * __expf(trans[j * 66 + 65]);
    float sw = warp_rsum(w);
    float gs = warp_rsum(gold);
    if (lane == 0) { S.fin[wih] = sw; S.wm[0][wih] = gs; }
    asm volatile("bar.sync %0, 64;" :: "r"(barid) : "memory");
    if (j == 0) {
        double logZ = (double)m0
                    + 0.6931471805599453 * (double)ks
                    + (double)__logf(S.fin[0] + S.fin[1]);
        double goldT = (double)(S.wm[0][0] + S.wm[0][1]);
        g_partial[b] = logZ - goldT;
    }
}

// Deterministic final reduction (fixed-order tree, double precision).
__global__ void crf_reduce_kernel(float* out, int B, int out_size)
{
    __shared__ double sh[256];
    int t = threadIdx.x;
    double s = 0.0;
    for (int i = t; i < B; i += 256) s += g_partial[i];
    sh[t] = s;
    __syncthreads();
    for (int w = 128; w > 0; w >>= 1) {
        if (t < w) sh[t] += sh[t + w];
        __syncthreads();
    }
    if (t == 0) out[0] = (float)sh[0];
    for (int i = t + 1; i < out_size; i += 256) out[i] = 0.0f;
}

extern "C" void kernel_launch(void* const* d_in, const int* in_sizes, int n_in,
                              void* d_out, int out_size)
{
    // Identify inputs by element count (robust to metadata ordering):
    //   trans = 66*66 = 4356, pred = largest, seq_len = smallest, ref = the rest.
    int it = -1;
    for (int i = 0; i < n_in; ++i)
        if (in_sizes[i] == 66 * 66) { it = i; break; }
    int ip = -1, is = -1;
    for (int i = 0; i < n_in; ++i) {
        if (i == it) continue;
        if (ip < 0 || in_sizes[i] > in_sizes[ip]) ip = i;
        if (is < 0 || in_sizes[i] < in_sizes[is]) is = i;
    }
    int ir = -1;
    for (int i = 0; i < n_in; ++i)
        if (i != it && i != ip && i != is) { ir = i; break; }

    const float* pred  = (const float*)d_in[ip];
    const float* trans = (const float*)d_in[it];
    const int*   ref   = (const int*)d_in[ir];
    const int*   slen  = (const int*)d_in[is];

    const int B = in_sizes[is];
    const int T = in_sizes[ir] / B;

    crf_forward_kernel<<<(B + 1) / 2, 128>>>(pred, trans, ref, slen, B, T);
    crf_reduce_kernel<<<1, 256>>>((float*)d_out, B, out_size);
}

// round 8
// speedup vs baseline: 1.5083x; 1.0787x over previous
#include <cuda_runtime.h>

// CRF negative log-likelihood, L=64 live states, exp-domain recursion.
//
//   v_t[j]  = (sum_i v_{t-1}[i] * E[i][j]) * exp(pred[b,t-1,j]) * 2^{-ex_t}
//   E[i][j] = exp(trans[i][j]);  ex_t = float-exponent of v_{t-1}[0]
//             (uniform exact power-of-two rescale; ks = sum ex_t, exact int)
//   logZ_b  = m0 + ks*ln2 + log( sum_j v_seq[j] * exp(trans[j][65]) )
//   gold_b  = sum_t pred[b,t,ref_t] + trans[64][ref_0]
//           + sum trans[ref_{t-1}][ref_t] + trans[ref_{seq-1}][65]
//
// One batch per 64-thread CTA (grid=B): cross-warp sync is a plain
// __syncthreads (BAR floor ~7, defer-blocking) instead of a named barrier.
// Final loss reduced by the last-finishing CTA in fixed index order
// (deterministic; counter self-resets for graph replay).

__device__ double g_partial[4096];
__device__ int    g_count;   // static zero-init; reset to 0 by last CTA each run

__device__ __forceinline__ float warp_rmax(float v) {
#pragma unroll
    for (int o = 16; o > 0; o >>= 1)
        v = fmaxf(v, __shfl_xor_sync(0xffffffffu, v, o));
    return v;
}
__device__ __forceinline__ float warp_rsum(float v) {
#pragma unroll
    for (int o = 16; o > 0; o >>= 1)
        v += __shfl_xor_sync(0xffffffffu, v, o);
    return v;
}

typedef unsigned long long u64;
__device__ __forceinline__ u64 ffma2(u64 a, u64 b, u64 c) {
    u64 d;
    asm("fma.rn.f32x2 %0, %1, %2, %3;" : "=l"(d) : "l"(a), "l"(b), "l"(c));
    return d;
}
__device__ __forceinline__ u64 fadd2(u64 a, u64 b) {
    u64 d;
    asm("add.rn.f32x2 %0, %1, %2;" : "=l"(d) : "l"(a), "l"(b));
    return d;
}
__device__ __forceinline__ u64 pack2(float lo, float hi) {
    u64 d;
    asm("mov.b64 %0, {%1, %2};" : "=l"(d) : "f"(lo), "f"(hi));
    return d;
}

__global__ void __launch_bounds__(64, 2)
crf_kernel(const float* __restrict__ pred,
           const float* __restrict__ trans,
           const int*   __restrict__ ref,
           const int*   __restrict__ slen,
           float* __restrict__ out,
           int B, int T, int out_size)
{
    __shared__ float4 e[2][16];     // double-buffered v vector (64 floats)
    __shared__ float  fin[4];
    __shared__ double red[64];
    __shared__ int    s_last;

    const int j    = threadIdx.x;   // state column, 0..63
    const int wih  = j >> 5;
    const int lane = j & 31;
    const int b    = blockIdx.x;    // grid = B exactly

    const float* pb  = pred + (size_t)b * T * 64;
    const int*   rb  = ref  + (size_t)b * T;
    const int    seq = slen[b];

    // E column j as 32 packed f32x2 pairs
    u64 E2[32];
#pragma unroll
    for (int p = 0; p < 32; ++p)
        E2[p] = pack2(__expf(trans[(2 * p) * 66 + j]),
                      __expf(trans[(2 * p + 1) * 66 + j]));

    // ---- gold path score (predicated fixed-stride loop for MLP) ----
    float gold = 0.0f;
    {
        int nk = (seq - j + 63) >> 6;   // iterations with t = j + 64k < seq
#pragma unroll 4
        for (int k = 0; k < nk; ++k) {
            int t  = j + (k << 6);
            int r  = rb[t];
            int rp = (t == 0) ? 64 : rb[t - 1];
            float g = pb[(size_t)t * 64 + r] + trans[rp * 66 + r];
            if (t == seq - 1) g += trans[r * 66 + 65];
            gold += g;
        }
    }

    // ---- bootstrap: v_1 = exp(alpha_1 - m0) ----
    float alpha1 = pb[j] + trans[64 * 66 + j];
    float wmax = warp_rmax(alpha1);
    if (lane == 0) fin[wih] = wmax;
    __syncthreads();
    float m0 = fmaxf(fin[0], fin[1]);
    float v  = __expf(alpha1 - m0);

    int ks = 0;

    // prefetch pipeline: P_cur = exp(pred row t-1) consumed at step t
    float P_cur = __expf(pb[(size_t)min(1, seq - 1) * 64 + j]);
    float pv_a  = pb[(size_t)min(2, seq - 1) * 64 + j];
    float pv_b  = pb[(size_t)min(3, seq - 1) * 64 + j];

    int par = 0;
    for (int t = 2; t <= seq; ++t) {
        // publish v_{t-1}
        reinterpret_cast<float*>(e[par])[j] = v;

        // rotate the prefetch pipeline BEFORE the sync: the LDG and MUFU
        // start during the (defer-blocking) barrier + LDS window.
        float Pn = __expf(pv_a);
        pv_a = pv_b;
        int tn = t + 2;
        int tc = tn < seq - 1 ? tn : seq - 1;
        pv_b = pb[(size_t)tc * 64 + j];

        __syncthreads();

        // scale factor from v_{t-1}[0] (exact power of two, zero-delay)
        float m = reinterpret_cast<const float*>(e[par])[0];

        // s_j = sum_i v_i * E[i][j]  — 16x LDS.128 + 32x FFMA2
        const ulonglong2* evv = reinterpret_cast<const ulonglong2*>(e[par]);
        u64 a0 = 0ull, a1 = 0ull, a2 = 0ull, a3 = 0ull;
#pragma unroll
        for (int k = 0; k < 16; k += 2) {
            ulonglong2 q0 = evv[k];
            ulonglong2 q1 = evv[k + 1];
            a0 = ffma2(q0.x, E2[2 * k + 0], a0);
            a1 = ffma2(q0.y, E2[2 * k + 1], a1);
            a2 = ffma2(q1.x, E2[2 * k + 2], a2);
            a3 = ffma2(q1.y, E2[2 * k + 3], a3);
        }

        int ex = (__float_as_int(m) >> 23) - 127;
        ks += ex;
        float factor = P_cur * __int_as_float((127 - ex) << 23);

        u64 s2 = fadd2(fadd2(a0, a2), fadd2(a1, a3));
        float slo, shi;
        asm("mov.b64 {%0, %1}, %2;" : "=f"(slo), "=f"(shi) : "l"(s2));
        v = (slo + shi) * factor;

        P_cur = Pn;
        par ^= 1;
    }

    // ---- logZ and per-batch loss ----
    float w  = v * __expf(trans[j * 66 + 65]);
    float sw = warp_rsum(w);
    float gs = warp_rsum(gold);
    if (lane == 0) { fin[wih] = sw; fin[2 + wih] = gs; }
    __syncthreads();
    if (j == 0) {
        double logZ = (double)m0
                    + 0.6931471805599453 * (double)ks
                    + (double)__logf(fin[0] + fin[1]);
        g_partial[b] = logZ - (double)(fin[2] + fin[3]);
        __threadfence();
        int c = atomicAdd(&g_count, 1);
        s_last = (c == (int)gridDim.x - 1) ? 1 : 0;
    }
    __syncthreads();

    // ---- last CTA: deterministic fixed-order final reduction ----
    if (s_last) {
        __threadfence();
        double s = 0.0;
        for (int i = j; i < B; i += 64) s += g_partial[i];
        red[j] = s;
        __syncthreads();
#pragma unroll
        for (int wd = 32; wd > 0; wd >>= 1) {
            if (j < wd) red[j] += red[j + wd];
            __syncthreads();
        }
        for (int i = j; i < out_size; i += 64)
            out[i] = (i == 0) ? (float)red[0] : 0.0f;
        if (j == 0) g_count = 0;   // reset for next graph replay
    }
}

extern "C" void kernel_launch(void* const* d_in, const int* in_sizes, int n_in,
                              void* d_out, int out_size)
{
    // Identify inputs by element count (robust to metadata ordering):
    //   trans = 66*66 = 4356, pred = largest, seq_len = smallest, ref = rest.
    int it = -1;
    for (int i = 0; i < n_in; ++i)
        if (in_sizes[i] == 66 * 66) { it = i; break; }
    int ip = -1, is = -1;
    for (int i = 0; i < n_in; ++i) {
        if (i == it) continue;
        if (ip < 0 || in_sizes[i] > in_sizes[ip]) ip = i;
        if (is < 0 || in_sizes[i] < in_sizes[is]) is = i;
    }
    int ir = -1;
    for (int i = 0; i < n_in; ++i)
        if (i != it && i != ip && i != is) { ir = i; break; }

    const float* pred  = (const float*)d_in[ip];
    const float* trans = (const float*)d_in[it];
    const int*   ref   = (const int*)d_in[ir];
    const int*   slen  = (const int*)d_in[is];

    const int B = in_sizes[is];
    const int T = in_sizes[ir] / B;

    crf_kernel<<<B, 64>>>(pred, trans, ref, slen, (float*)d_out, B, T, out_size);
}